// round 11
// baseline (speedup 1.0000x reference)
#include <cuda_runtime.h>
#include <cuda_fp16.h>
#include <cstdint>

#define B_  64
#define T_  320
#define E_  1024
#define H_  16
#define P_  4096
#define M_  (B_ * T_)          // 20480 tokens
#define EPS 1e-5f
#define SCALE 0.03125f          // E^-0.5

typedef unsigned u32;
typedef __half fp16;

// ---------------- scratch (device globals) ----------------
__device__ fp16 g_h[(size_t)M_ * E_];
__device__ fp16 g_w3[(size_t)E_ * 3 * E_];      // [K=1024][N=3072]
__device__ fp16 g_wo[(size_t)E_ * E_];          // [K][N]
__device__ fp16 g_w1[(size_t)E_ * P_];          // [K=1024][N=4096]
__device__ fp16 g_w2[(size_t)P_ * E_];          // [K=4096][N=1024]
__device__ fp16 g_qkv[(size_t)M_ * 3 * E_];     // fp16 q|k|v
__device__ fp16 g_attn[(size_t)M_ * E_];
__device__ float g_x2[(size_t)M_ * E_];
__device__ fp16 g_u[(size_t)M_ * P_];

// ---------------- helpers ----------------
__device__ __forceinline__ u32 smem_u32(const void* p) {
    return (u32)__cvta_generic_to_shared(p);
}
__device__ __forceinline__ u32 pack_h2(float a, float b) {
    union { __half2 h; u32 u; } c;
    c.h = __floats2half2_rn(a, b);
    return c.u;
}
__device__ __forceinline__ void cp16(u32 dst, const void* src) {
    asm volatile("cp.async.cg.shared.global [%0], [%1], 16;" :: "r"(dst), "l"(src));
}
__device__ __forceinline__ void cp_commit() { asm volatile("cp.async.commit_group;"); }
__device__ __forceinline__ void cp_wait0() { asm volatile("cp.async.wait_group 0;"); }
__device__ __forceinline__ void cp_wait1() { asm volatile("cp.async.wait_group 1;"); }

__device__ __forceinline__ void ldsm4(u32 addr, u32& r0, u32& r1, u32& r2, u32& r3) {
    asm volatile("ldmatrix.sync.aligned.m8n8.x4.shared.b16 {%0,%1,%2,%3}, [%4];"
                 : "=r"(r0), "=r"(r1), "=r"(r2), "=r"(r3) : "r"(addr));
}
__device__ __forceinline__ void ldsm4t(u32 addr, u32& r0, u32& r1, u32& r2, u32& r3) {
    asm volatile("ldmatrix.sync.aligned.m8n8.x4.trans.shared.b16 {%0,%1,%2,%3}, [%4];"
                 : "=r"(r0), "=r"(r1), "=r"(r2), "=r"(r3) : "r"(addr));
}
__device__ __forceinline__ void ldsm2(u32 addr, u32& r0, u32& r1) {
    asm volatile("ldmatrix.sync.aligned.m8n8.x2.shared.b16 {%0,%1}, [%2];"
                 : "=r"(r0), "=r"(r1) : "r"(addr));
}
__device__ __forceinline__ void ldsm2t(u32 addr, u32& r0, u32& r1) {
    asm volatile("ldmatrix.sync.aligned.m8n8.x2.trans.shared.b16 {%0,%1}, [%2];"
                 : "=r"(r0), "=r"(r1) : "r"(addr));
}
__device__ __forceinline__ void mma_fp16(float* c, const u32* a, const u32* b) {
    asm volatile("mma.sync.aligned.m16n8k16.row.col.f32.f16.f16.f32 "
                 "{%0,%1,%2,%3}, {%4,%5,%6,%7}, {%8,%9}, {%0,%1,%2,%3};"
                 : "+f"(c[0]), "+f"(c[1]), "+f"(c[2]), "+f"(c[3])
                 : "r"(a[0]), "r"(a[1]), "r"(a[2]), "r"(a[3]), "r"(b[0]), "r"(b[1]));
}
__device__ __forceinline__ void h2store4(float4 v, fp16* dst, size_t idx) {
    uint2 u;
    u.x = pack_h2(v.x, v.y);
    u.y = pack_h2(v.z, v.w);
    *(uint2*)(dst + idx) = u;
}

// ---------------- weight prep ----------------
__global__ void pack_w3_kernel(const float* __restrict__ Wq, const float* __restrict__ Wk,
                               const float* __restrict__ Wv, fp16* __restrict__ w) {
    int idx = blockIdx.x * 256 + threadIdx.x;
    int k = idx / 3072, n = idx % 3072;
    int which = n >> 10, rem = n & 1023, hh = rem >> 6, d = rem & 63;
    const float* W = (which == 0) ? Wq : (which == 1) ? Wk : Wv;
    w[idx] = __float2half_rn(W[(size_t)hh * E_ * 64 + (size_t)k * 64 + d]);
}

__global__ void quant_w_kernel(const float* __restrict__ src, fp16* __restrict__ dst, int n) {
    int idx = blockIdx.x * 256 + threadIdx.x;
    if (idx < n) dst[idx] = __float2half_rn(src[idx]);
}

// ---------------- layernorm (emits fp16) ----------------
__device__ __forceinline__ float blockSum256(float v, float* sh) {
    __syncthreads();
    #pragma unroll
    for (int o = 16; o > 0; o >>= 1) v += __shfl_xor_sync(0xffffffffu, v, o);
    if ((threadIdx.x & 31) == 0) sh[threadIdx.x >> 5] = v;
    __syncthreads();
    if (threadIdx.x < 32) {
        float t = (threadIdx.x < 8) ? sh[threadIdx.x] : 0.0f;
        #pragma unroll
        for (int o = 4; o > 0; o >>= 1) t += __shfl_xor_sync(0xffffffffu, t, o);
        if (threadIdx.x == 0) sh[0] = t;
    }
    __syncthreads();
    return sh[0];
}

__global__ void ln_kernel(const float* __restrict__ x, const float* __restrict__ w,
                          const float* __restrict__ bb, fp16* __restrict__ out) {
    __shared__ float sh[8];
    size_t row = blockIdx.x;
    int tid = threadIdx.x;
    const float4 v = ((const float4*)(x + row * E_))[tid];
    float s = v.x + v.y + v.z + v.w;
    s = blockSum256(s, sh);
    float mu = s * (1.0f / E_);
    float dx = v.x - mu, dy = v.y - mu, dz = v.z - mu, dw = v.w - mu;
    float ss = dx * dx + dy * dy + dz * dz + dw * dw;
    ss = blockSum256(ss, sh);
    float inv = rsqrtf(ss * (1.0f / E_) + EPS);
    float4 w4 = ((const float4*)w)[tid];
    float4 b4 = ((const float4*)bb)[tid];
    float4 r;
    r.x = dx * inv * w4.x + b4.x;
    r.y = dy * inv * w4.y + b4.y;
    r.z = dz * inv * w4.z + b4.z;
    r.w = dw * inv * w4.w + b4.w;
    h2store4(r, out, row * E_ + tid * 4);
}

// ---------------- single-pass fp16 tensor-core GEMM, 3-stage pipeline ----------------
// CTA 128x128, 4 warps (2x2), warp tile 64x64. K-stage 32.
// smem per stage: A[128][40] (80B pitch), B[32][136] (272B pitch)
#define A_BYTES 10240
#define B_BYTES 8704
#define STAGE_BYTES (A_BYTES + B_BYTES)
#define SM_TOTAL (3 * STAGE_BYTES)      // 56832

template <bool BIAS, bool RESID, bool RELU, bool HALFOUT>
__global__ __launch_bounds__(128, 2) void gemm_mma_kernel(
    const fp16* __restrict__ Aw, const fp16* __restrict__ Bw,
    const float* __restrict__ bias, const float* __restrict__ Rm,
    float* __restrict__ Cf, fp16* __restrict__ Ch,
    int N, int K) {
    extern __shared__ char sm[];
    const u32 smb = smem_u32(sm);

    int tid = threadIdx.x;
    int lane = tid & 31, wid = tid >> 5;
    int warpM = (wid >> 1) * 64, warpN = (wid & 1) * 64;
    int bm = blockIdx.y * 128, bn = blockIdx.x * 128;

    int a_cr = tid >> 2, a_cc = tid & 3;
    int b_cr = tid >> 4, b_cc = tid & 15;
    u32 a_dst0 = a_cr * 80 + a_cc * 16;
    u32 b_dst0 = b_cr * 272 + b_cc * 16;

    u32 a_off = (warpM + (lane & 15)) * 80 + (lane >> 4) * 16;
    u32 b_off = (lane & 15) * 272 + warpN * 2 + (lane >> 4) * 16;

    auto load_stage = [&](u32 sb, int k0) {
        #pragma unroll
        for (int c = 0; c < 4; c++) {
            cp16(sb + a_dst0 + c * 32 * 80,
                 Aw + (size_t)(bm + a_cr + c * 32) * K + k0 + a_cc * 8);
            cp16(sb + A_BYTES + b_dst0 + c * 8 * 272,
                 Bw + (size_t)(k0 + b_cr + c * 8) * N + bn + b_cc * 8);
        }
        cp_commit();
    };

    float acc[4][8][4];
    #pragma unroll
    for (int i = 0; i < 4; i++)
        #pragma unroll
        for (int j = 0; j < 8; j++)
            #pragma unroll
            for (int c = 0; c < 4; c++) acc[i][j][c] = 0.0f;

    const int nk = K >> 5;

    // prologue: stages 0 and 1 in flight
    load_stage(smb, 0);
    load_stage(smb + STAGE_BYTES, 32);

    for (int kt = 0; kt < nk; kt++) {
        if (kt + 1 < nk) cp_wait1(); else cp_wait0();
        __syncthreads();
        u32 cur = smb + (u32)(kt % 3) * STAGE_BYTES;

        if (kt + 2 < nk)
            load_stage(smb + (u32)((kt + 2) % 3) * STAGE_BYTES, (kt + 2) * 32);

        #pragma unroll
        for (int ks = 0; ks < 2; ks++) {
            u32 bw[8][2];
            #pragma unroll
            for (int nj = 0; nj < 4; nj++) {
                u32 ba = cur + A_BYTES + b_off + nj * 32 + ks * 4352;
                ldsm4t(ba, bw[2 * nj][0], bw[2 * nj][1], bw[2 * nj + 1][0], bw[2 * nj + 1][1]);
            }
            #pragma unroll
            for (int mi = 0; mi < 4; mi++) {
                u32 ar[4];
                u32 aa = cur + a_off + mi * 1280 + ks * 32;
                ldsm4(aa, ar[0], ar[1], ar[2], ar[3]);
                #pragma unroll
                for (int ni = 0; ni < 8; ni++)
                    mma_fp16(acc[mi][ni], ar, bw[ni]);
            }
        }
    }

    // epilogue
    int g = lane >> 2, tg = lane & 3;
    #pragma unroll
    for (int mi = 0; mi < 4; mi++) {
        #pragma unroll
        for (int ni = 0; ni < 8; ni++) {
            int col = bn + warpN + ni * 8 + tg * 2;
            #pragma unroll
            for (int half = 0; half < 2; half++) {
                int row = bm + warpM + mi * 16 + g + half * 8;
                float vx = acc[mi][ni][half * 2 + 0];
                float vy = acc[mi][ni][half * 2 + 1];
                if (BIAS) {
                    float2 bb = *(const float2*)(bias + col);
                    vx += bb.x; vy += bb.y;
                }
                size_t off = (size_t)row * N + col;
                if (RESID) {
                    float2 rr = *(const float2*)(Rm + off);
                    vx += rr.x; vy += rr.y;
                }
                if (RELU) { vx = fmaxf(vx, 0.0f); vy = fmaxf(vy, 0.0f); }
                if (HALFOUT) {
                    u32 hv = pack_h2(vx, vy);
                    *(u32*)(Ch + off) = hv;
                } else {
                    float2 o; o.x = vx; o.y = vy;
                    *(float2*)(Cf + off) = o;
                }
            }
        }
    }
}

// ---------------- tensor-core flash attention (cp.async KV pipeline) ----------------
// K stored row-major [kc][d] and consumed with NON-transposed ldmatrix:
// for S = Q K^T with mma.row.col, K[kc][d] IS B in col-major layout.
#define ATP 72
__global__ __launch_bounds__(128) void attn_mma_kernel(const fp16* __restrict__ qkv,
                                                       fp16* __restrict__ oh) {
    __shared__ fp16 sQ[64 * ATP];
    __shared__ fp16 sK[2][64 * ATP];
    __shared__ fp16 sV[2][64 * ATP];

    int qt = blockIdx.x, h = blockIdx.y, b = blockIdx.z;
    int tid = threadIdx.x, lane = tid & 31, w = tid >> 5;
    int g = lane >> 2, tg = lane & 3;
    int t0 = qt * 64;
    size_t base = (size_t)b * T_ * 3072;

    const u32 sQa = smem_u32(sQ);
    const u32 sKa0 = smem_u32(sK);
    const u32 sVa0 = smem_u32(sV);

    // per-thread copy coords: 4 chunks of 16B per tile
    int cp_r[4], cp_c[4];
    #pragma unroll
    for (int i = 0; i < 4; i++) {
        int idx = i * 128 + tid;
        cp_r[i] = idx >> 3;
        cp_c[i] = (idx & 7) * 8;
    }

    // group 0: Q + KV tile 0
    #pragma unroll
    for (int i = 0; i < 4; i++)
        cp16(sQa + cp_r[i] * 144 + cp_c[i] * 2,
             qkv + base + (size_t)(t0 + cp_r[i]) * 3072 + h * 64 + cp_c[i]);
    #pragma unroll
    for (int i = 0; i < 4; i++) {
        cp16(sKa0 + cp_r[i] * 144 + cp_c[i] * 2,
             qkv + base + (size_t)cp_r[i] * 3072 + 1024 + h * 64 + cp_c[i]);
        cp16(sVa0 + cp_r[i] * 144 + cp_c[i] * 2,
             qkv + base + (size_t)cp_r[i] * 3072 + 2048 + h * 64 + cp_c[i]);
    }
    cp_commit();

    float o[8][4];
    #pragma unroll
    for (int j = 0; j < 8; j++)
        #pragma unroll
        for (int c = 0; c < 4; c++) o[j][c] = 0.0f;
    float mrow[2] = {-1e30f, -1e30f};
    float lrow[2] = {0.0f, 0.0f};

    int buf = 0;
    for (int ktile = 0; ktile <= qt; ++ktile) {
        cp_wait0();
        __syncthreads();
        int nbuf = buf ^ 1;
        if (ktile < qt) {
            int k1 = (ktile + 1) * 64;
            u32 kd = sKa0 + (u32)nbuf * (64 * ATP * 2);
            u32 vd = sVa0 + (u32)nbuf * (64 * ATP * 2);
            #pragma unroll
            for (int i = 0; i < 4; i++) {
                cp16(kd + cp_r[i] * 144 + cp_c[i] * 2,
                     qkv + base + (size_t)(k1 + cp_r[i]) * 3072 + 1024 + h * 64 + cp_c[i]);
                cp16(vd + cp_r[i] * 144 + cp_c[i] * 2,
                     qkv + base + (size_t)(k1 + cp_r[i]) * 3072 + 2048 + h * 64 + cp_c[i]);
            }
            cp_commit();
        }

        u32 sKb = sKa0 + (u32)buf * (64 * ATP * 2);
        u32 sVb = sVa0 + (u32)buf * (64 * ATP * 2);

        // S = Q(16x64) @ K^T
        float cs[8][4];
        #pragma unroll
        for (int j = 0; j < 8; j++)
            #pragma unroll
            for (int c = 0; c < 4; c++) cs[j][c] = 0.0f;

        #pragma unroll
        for (int ks = 0; ks < 4; ks++) {
            u32 ar[4];
            u32 aa = sQa + (w * 16 + (lane & 7) + ((lane >> 3) & 1) * 8) * 144
                   + (lane >> 4) * 16 + ks * 32;
            ldsm4(aa, ar[0], ar[1], ar[2], ar[3]);
            #pragma unroll
            for (int j = 0; j < 8; j++) {
                u32 bw[2];
                // non-trans: lanes 0-15 address rows kc = 8j..8j+7, d-halves ks*16 + (0|8)
                ldsm2(sKb + (8 * j + (lane & 7)) * 144 + ks * 32 + ((lane >> 3) & 1) * 16,
                      bw[0], bw[1]);
                mma_fp16(cs[j], ar, bw);
            }
        }

        #pragma unroll
        for (int j = 0; j < 8; j++)
            #pragma unroll
            for (int c = 0; c < 4; c++) cs[j][c] *= SCALE;
        if (ktile == qt) {
            int r0 = w * 16 + g, r1 = r0 + 8;
            #pragma unroll
            for (int j = 0; j < 8; j++) {
                int c0 = 8 * j + 2 * tg;
                if (c0 > r0) cs[j][0] = -1e30f;
                if (c0 + 1 > r0) cs[j][1] = -1e30f;
                if (c0 > r1) cs[j][2] = -1e30f;
                if (c0 + 1 > r1) cs[j][3] = -1e30f;
            }
        }

        float al[2];
        #pragma unroll
        for (int hr = 0; hr < 2; hr++) {
            float mx = -1e30f;
            #pragma unroll
            for (int j = 0; j < 8; j++)
                mx = fmaxf(mx, fmaxf(cs[j][hr * 2], cs[j][hr * 2 + 1]));
            mx = fmaxf(mx, __shfl_xor_sync(0xffffffffu, mx, 1));
            mx = fmaxf(mx, __shfl_xor_sync(0xffffffffu, mx, 2));
            float mn = fmaxf(mrow[hr], mx);
            al[hr] = __expf(mrow[hr] - mn);
            float rs = 0.0f;
            #pragma unroll
            for (int j = 0; j < 8; j++) {
                float p0 = __expf(cs[j][hr * 2] - mn);
                float p1 = __expf(cs[j][hr * 2 + 1] - mn);
                cs[j][hr * 2] = p0;
                cs[j][hr * 2 + 1] = p1;
                rs += p0 + p1;
            }
            rs += __shfl_xor_sync(0xffffffffu, rs, 1);
            rs += __shfl_xor_sync(0xffffffffu, rs, 2);
            lrow[hr] = lrow[hr] * al[hr] + rs;
            mrow[hr] = mn;
        }
        #pragma unroll
        for (int j = 0; j < 8; j++) {
            o[j][0] *= al[0]; o[j][1] *= al[0];
            o[j][2] *= al[1]; o[j][3] *= al[1];
        }

        // P fragments (C-frag -> A-frag identity)
        u32 aP[4][4];
        #pragma unroll
        for (int st = 0; st < 4; st++) {
            aP[st][0] = pack_h2(cs[2 * st][0], cs[2 * st][1]);
            aP[st][1] = pack_h2(cs[2 * st][2], cs[2 * st][3]);
            aP[st][2] = pack_h2(cs[2 * st + 1][0], cs[2 * st + 1][1]);
            aP[st][3] = pack_h2(cs[2 * st + 1][2], cs[2 * st + 1][3]);
        }

        // O += P(16x64) @ V(64x64)  (V [kc][d] needs trans ldmatrix)
        #pragma unroll
        for (int st = 0; st < 4; st++) {
            #pragma unroll
            for (int j2 = 0; j2 < 8; j2++) {
                u32 bw[2];
                ldsm2t(sVb + (st * 16 + (lane & 15)) * 144 + j2 * 16, bw[0], bw[1]);
                mma_fp16(o[j2], aP[st], bw);
            }
        }
        buf = nbuf;
    }

    float inv0 = 1.0f / lrow[0], inv1 = 1.0f / lrow[1];
    int r0 = t0 + w * 16 + g;
    size_t ob = ((size_t)b * T_ + r0) * E_ + h * 64;
    #pragma unroll
    for (int j = 0; j < 8; j++) {
        int col = 8 * j + 2 * tg;
        *(u32*)(oh + ob + col) = pack_h2(o[j][0] * inv0, o[j][1] * inv0);
        *(u32*)(oh + ob + 8 * E_ + col) = pack_h2(o[j][2] * inv1, o[j][3] * inv1);
    }
}

// ---------------- launch ----------------
extern "C" void kernel_launch(void* const* d_in, const int* in_sizes, int n_in,
                              void* d_out, int out_size) {
    const float* x    = (const float*)d_in[0];
    const float* Wq   = (const float*)d_in[1];
    const float* Wk   = (const float*)d_in[2];
    const float* Wv   = (const float*)d_in[3];
    const float* Wo   = (const float*)d_in[4];
    const float* bo   = (const float*)d_in[5];
    const float* W1   = (const float*)d_in[6];
    const float* b1   = (const float*)d_in[7];
    const float* W2   = (const float*)d_in[8];
    const float* b2   = (const float*)d_in[9];
    const float* ln1w = (const float*)d_in[10];
    const float* ln1b = (const float*)d_in[11];
    const float* ln2w = (const float*)d_in[12];
    const float* ln2b = (const float*)d_in[13];
    float* out = (float*)d_out;

    fp16 *h, *w3, *wo, *w1, *w2, *qkv, *attn, *u;
    float *x2;
    cudaGetSymbolAddress((void**)&h, g_h);
    cudaGetSymbolAddress((void**)&w3, g_w3);
    cudaGetSymbolAddress((void**)&wo, g_wo);
    cudaGetSymbolAddress((void**)&w1, g_w1);
    cudaGetSymbolAddress((void**)&w2, g_w2);
    cudaGetSymbolAddress((void**)&qkv, g_qkv);
    cudaGetSymbolAddress((void**)&attn, g_attn);
    cudaGetSymbolAddress((void**)&x2, g_x2);
    cudaGetSymbolAddress((void**)&u, g_u);

    cudaFuncSetAttribute(gemm_mma_kernel<false, false, false, true>,
                         cudaFuncAttributeMaxDynamicSharedMemorySize, SM_TOTAL);
    cudaFuncSetAttribute(gemm_mma_kernel<true, true, false, false>,
                         cudaFuncAttributeMaxDynamicSharedMemorySize, SM_TOTAL);
    cudaFuncSetAttribute(gemm_mma_kernel<true, false, true, true>,
                         cudaFuncAttributeMaxDynamicSharedMemorySize, SM_TOTAL);

    // weight prep
    pack_w3_kernel<<<(3 * E_ * E_) / 256, 256>>>(Wq, Wk, Wv, w3);
    quant_w_kernel<<<(E_ * E_) / 256, 256>>>(Wo, wo, E_ * E_);
    quant_w_kernel<<<(E_ * P_) / 256, 256>>>(W1, w1, E_ * P_);
    quant_w_kernel<<<(P_ * E_) / 256, 256>>>(W2, w2, P_ * E_);

    // LN1
    ln_kernel<<<M_, 256>>>(x, ln1w, ln1b, h);

    // QKV -> fp16
    gemm_mma_kernel<false, false, false, true><<<dim3(3072 / 128, M_ / 128), 128, SM_TOTAL>>>(
        h, w3, nullptr, nullptr, nullptr, qkv, 3072, E_);

    // attention (tensor cores)
    attn_mma_kernel<<<dim3(T_ / 64, H_, B_), 128>>>(qkv, attn);

    // out-proj + bias + residual(x) -> fp32 x2
    gemm_mma_kernel<true, true, false, false><<<dim3(E_ / 128, M_ / 128), 128, SM_TOTAL>>>(
        attn, wo, bo, x, x2, nullptr, E_, E_);

    // LN2
    ln_kernel<<<M_, 256>>>(x2, ln2w, ln2b, h);

    // FFN1: relu -> fp16 u
    gemm_mma_kernel<true, false, true, true><<<dim3(P_ / 128, M_ / 128), 128, SM_TOTAL>>>(
        h, w1, b1, nullptr, nullptr, u, P_, E_);

    // FFN2 -> out fp32
    gemm_mma_kernel<true, true, false, false><<<dim3(E_ / 128, M_ / 128), 128, SM_TOTAL>>>(
        u, w2, b2, x2, out, nullptr, E_, P_);
}